// round 2
// baseline (speedup 1.0000x reference)
#include <cuda_runtime.h>

// out[e] = sigmoid( dot( x[src[e], 0:128], x[dst[e], 128:256] ) )
// x: [100000, 256] fp32.
// edge_label_index: [2, N_EDGES] — int32 on device (JAX x64 disabled downcasts
// the reference's jnp.int64 to int32).
// One warp per edge: lane i loads float4 i of each 128-float half-row.

#define HIDDEN 256
#define HALF   128

__global__ __launch_bounds__(256)
void edge_dot_sigmoid_kernel(const float* __restrict__ x,
                             const int* __restrict__ eidx,
                             float* __restrict__ out,
                             int n_edges)
{
    int warp = (blockIdx.x * blockDim.x + threadIdx.x) >> 5;
    int lane = threadIdx.x & 31;
    if (warp >= n_edges) return;

    // Warp-uniform index loads (broadcast: one request per warp each).
    int s = __ldg(&eidx[warp]);
    int d = __ldg(&eidx[n_edges + warp]);

    const float4* __restrict__ srow =
        reinterpret_cast<const float4*>(x + (long long)s * HIDDEN);        // cols [0,128)
    const float4* __restrict__ drow =
        reinterpret_cast<const float4*>(x + (long long)d * HIDDEN + HALF); // cols [128,256)

    float4 a = __ldg(&srow[lane]);
    float4 b = __ldg(&drow[lane]);

    float dot = a.x * b.x + a.y * b.y + a.z * b.z + a.w * b.w;

    #pragma unroll
    for (int off = 16; off > 0; off >>= 1)
        dot += __shfl_xor_sync(0xffffffffu, dot, off);

    if (lane == 0)
        out[warp] = 1.0f / (1.0f + __expf(-dot));
}

extern "C" void kernel_launch(void* const* d_in, const int* in_sizes, int n_in,
                              void* d_out, int out_size)
{
    const float* x    = (const float*)d_in[0];
    const int*   eidx = (const int*)d_in[1];
    float*       out  = (float*)d_out;

    int n_edges = in_sizes[1] / 2;   // edge_label_index has 2*N_EDGES elements

    const int threads = 256;                       // 8 warps/block
    int warps_per_block = threads / 32;
    int blocks = (n_edges + warps_per_block - 1) / warps_per_block;

    edge_dot_sigmoid_kernel<<<blocks, threads>>>(x, eidx, out, n_edges);
}

// round 3
// speedup vs baseline: 1.7379x; 1.7379x over previous
#include <cuda_runtime.h>

// out[e] = sigmoid( dot( x[src[e], 0:128], x[dst[e], 128:256] ) )
// x: [100000, 256] fp32. edge_label_index: [2, N_EDGES] int32 on device.
//
// 4 edges per warp: batch 8 gather LDG.128s per lane for MLP, interleave the
// 4 shuffle reductions, one STG.128 per warp for the 4 outputs.

#define HIDDEN 256
#define HALF   128
#define EPW    4     // edges per warp

__global__ __launch_bounds__(256)
void edge_dot_sigmoid_kernel(const float* __restrict__ x,
                             const int* __restrict__ eidx,
                             float* __restrict__ out,
                             int n_edges)
{
    int warp = (blockIdx.x * blockDim.x + threadIdx.x) >> 5;
    int lane = threadIdx.x & 31;
    int base = warp * EPW;
    if (base >= n_edges) return;

    if (base + EPW <= n_edges) {
        // Fast path: full group of 4 edges.
        // Warp-uniform vector index loads (one 16B request each).
        int4 s4 = __ldg(reinterpret_cast<const int4*>(eidx + base));
        int4 d4 = __ldg(reinterpret_cast<const int4*>(eidx + n_edges + base));
        int s[EPW] = {s4.x, s4.y, s4.z, s4.w};
        int d[EPW] = {d4.x, d4.y, d4.z, d4.w};

        // Issue all 8 gathers before any math (MLP=8 per lane).
        float4 a[EPW], b[EPW];
        #pragma unroll
        for (int k = 0; k < EPW; k++)
            a[k] = __ldg(reinterpret_cast<const float4*>(
                       x + (long long)s[k] * HIDDEN) + lane);
        #pragma unroll
        for (int k = 0; k < EPW; k++)
            b[k] = __ldg(reinterpret_cast<const float4*>(
                       x + (long long)d[k] * HIDDEN + HALF) + lane);

        float dot[EPW];
        #pragma unroll
        for (int k = 0; k < EPW; k++)
            dot[k] = a[k].x * b[k].x + a[k].y * b[k].y
                   + a[k].z * b[k].z + a[k].w * b[k].w;

        // 4 independent butterfly reductions — chains overlap.
        #pragma unroll
        for (int off = 16; off > 0; off >>= 1) {
            #pragma unroll
            for (int k = 0; k < EPW; k++)
                dot[k] += __shfl_xor_sync(0xffffffffu, dot[k], off);
        }

        if (lane == 0) {
            float4 r;
            r.x = 1.0f / (1.0f + __expf(-dot[0]));
            r.y = 1.0f / (1.0f + __expf(-dot[1]));
            r.z = 1.0f / (1.0f + __expf(-dot[2]));
            r.w = 1.0f / (1.0f + __expf(-dot[3]));
            *reinterpret_cast<float4*>(out + base) = r;
        }
    } else {
        // Tail: up to 3 edges, scalar path.
        for (int e = base; e < n_edges; e++) {
            int s = __ldg(&eidx[e]);
            int d = __ldg(&eidx[n_edges + e]);
            float4 a = __ldg(reinterpret_cast<const float4*>(
                           x + (long long)s * HIDDEN) + lane);
            float4 b = __ldg(reinterpret_cast<const float4*>(
                           x + (long long)d * HIDDEN + HALF) + lane);
            float dot = a.x * b.x + a.y * b.y + a.z * b.z + a.w * b.w;
            #pragma unroll
            for (int off = 16; off > 0; off >>= 1)
                dot += __shfl_xor_sync(0xffffffffu, dot, off);
            if (lane == 0)
                out[e] = 1.0f / (1.0f + __expf(-dot));
        }
    }
}

extern "C" void kernel_launch(void* const* d_in, const int* in_sizes, int n_in,
                              void* d_out, int out_size)
{
    const float* x    = (const float*)d_in[0];
    const int*   eidx = (const int*)d_in[1];
    float*       out  = (float*)d_out;

    int n_edges = in_sizes[1] / 2;   // edge_label_index has 2*N_EDGES elements

    const int threads = 256;                       // 8 warps/block
    int warps_per_block = threads / 32;
    int edges_per_block = warps_per_block * EPW;
    int blocks = (n_edges + edges_per_block - 1) / edges_per_block;

    edge_dot_sigmoid_kernel<<<blocks, threads>>>(x, eidx, out, n_edges);
}

// round 6
// speedup vs baseline: 2.0711x; 1.1918x over previous
#include <cuda_runtime.h>

// out[e] = sigmoid( dot( x[src[e], 0:128], x[dst[e], 128:256] ) )
// x: [100000, 256] fp32. edge_label_index: [2, N_EDGES] int32 on device.
//
// 8 edges per warp, MLP=16 gather LDG.128s per lane.
// Merging butterfly: 16 SHFLs reduce all 8 edge dots at once; after the tree,
// lane l holds the sum for edge (l & 7), so lanes 0-7 do 8 parallel sigmoids
// and one coalesced 32B store.

#define HIDDEN 256
#define HALF   128
#define EPW    8     // edges per warp

__device__ __forceinline__ float sigmoidf(float v)
{
    return 1.0f / (1.0f + __expf(-v));
}

__global__ __launch_bounds__(256)
void edge_dot_sigmoid_kernel(const float* __restrict__ x,
                             const int* __restrict__ eidx,
                             float* __restrict__ out,
                             int n_edges)
{
    int warp = (blockIdx.x * blockDim.x + threadIdx.x) >> 5;
    int lane = threadIdx.x & 31;
    int base = warp * EPW;
    if (base >= n_edges) return;

    if (base + EPW <= n_edges) {
        // Warp-uniform vector index loads (16B requests).
        int4 s0 = __ldg(reinterpret_cast<const int4*>(eidx + base));
        int4 s1 = __ldg(reinterpret_cast<const int4*>(eidx + base + 4));
        int4 d0 = __ldg(reinterpret_cast<const int4*>(eidx + n_edges + base));
        int4 d1 = __ldg(reinterpret_cast<const int4*>(eidx + n_edges + base + 4));
        int s[EPW] = {s0.x, s0.y, s0.z, s0.w, s1.x, s1.y, s1.z, s1.w};
        int d[EPW] = {d0.x, d0.y, d0.z, d0.w, d1.x, d1.y, d1.z, d1.w};

        // Issue all 16 gathers before any math (MLP=16 per lane).
        float4 a[EPW], b[EPW];
        #pragma unroll
        for (int k = 0; k < EPW; k++)
            a[k] = __ldg(reinterpret_cast<const float4*>(
                       x + (long long)s[k] * HIDDEN) + lane);
        #pragma unroll
        for (int k = 0; k < EPW; k++)
            b[k] = __ldg(reinterpret_cast<const float4*>(
                       x + (long long)d[k] * HIDDEN + HALF) + lane);

        float v[EPW];
        #pragma unroll
        for (int k = 0; k < EPW; k++)
            v[k] = a[k].x * b[k].x + a[k].y * b[k].y
                 + a[k].z * b[k].z + a[k].w * b[k].w;

        // Merging butterfly: 8 -> 4 -> 2 -> 1 arrays, then finish the tree.
        // After level L, the array entry carried by a lane depends on lane
        // bit (L-1); parity classes keep different edges separated.
        float m0[4];
        #pragma unroll
        for (int k = 0; k < 4; k++) {
            float e0 = v[2*k]   + __shfl_xor_sync(0xffffffffu, v[2*k],   1);
            float e1 = v[2*k+1] + __shfl_xor_sync(0xffffffffu, v[2*k+1], 1);
            m0[k] = (lane & 1) ? e1 : e0;
        }
        float m1[2];
        #pragma unroll
        for (int k = 0; k < 2; k++) {
            float e0 = m0[2*k]   + __shfl_xor_sync(0xffffffffu, m0[2*k],   2);
            float e1 = m0[2*k+1] + __shfl_xor_sync(0xffffffffu, m0[2*k+1], 2);
            m1[k] = (lane & 2) ? e1 : e0;
        }
        float e0 = m1[0] + __shfl_xor_sync(0xffffffffu, m1[0], 4);
        float e1 = m1[1] + __shfl_xor_sync(0xffffffffu, m1[1], 4);
        float m2 = (lane & 4) ? e1 : e0;
        m2 += __shfl_xor_sync(0xffffffffu, m2, 8);
        m2 += __shfl_xor_sync(0xffffffffu, m2, 16);
        // lane l now holds the full dot for edge (l & 7).

        if (lane < EPW)
            out[base + lane] = sigmoidf(m2);
    } else {
        // Tail: up to EPW-1 edges, scalar path.
        for (int e = base; e < n_edges; e++) {
            int s = __ldg(&eidx[e]);
            int d = __ldg(&eidx[n_edges + e]);
            float4 a = __ldg(reinterpret_cast<const float4*>(
                           x + (long long)s * HIDDEN) + lane);
            float4 b = __ldg(reinterpret_cast<const float4*>(
                           x + (long long)d * HIDDEN + HALF) + lane);
            float dot = a.x * b.x + a.y * b.y + a.z * b.z + a.w * b.w;
            #pragma unroll
            for (int off = 16; off > 0; off >>= 1)
                dot += __shfl_xor_sync(0xffffffffu, dot, off);
            if (lane == 0)
                out[e] = sigmoidf(dot);
        }
    }
}

extern "C" void kernel_launch(void* const* d_in, const int* in_sizes, int n_in,
                              void* d_out, int out_size)
{
    const float* x    = (const float*)d_in[0];
    const int*   eidx = (const int*)d_in[1];
    float*       out  = (float*)d_out;

    int n_edges = in_sizes[1] / 2;   // edge_label_index has 2*N_EDGES elements

    const int threads = 256;                       // 8 warps/block
    int warps_per_block = threads / 32;
    int edges_per_block = warps_per_block * EPW;
    int blocks = (n_edges + edges_per_block - 1) / edges_per_block;

    edge_dot_sigmoid_kernel<<<blocks, threads>>>(x, eidx, out, n_edges);
}

// round 7
// speedup vs baseline: 2.0896x; 1.0089x over previous
#include <cuda_runtime.h>

// out[e] = sigmoid( dot( x[src[e], 0:128], x[dst[e], 128:256] ) )
// x: [100000, 256] fp32. edge_label_index: [2, N_EDGES] int32 on device.
//
// 16 edges per warp, up to 32 gather LDG.128s in flight per lane.
// Merging butterfly: 31 SHFLs reduce all 16 edge dots at once; after the
// tree, lane l holds the sum for edge (l & 15), so lanes 0-15 do 16 parallel
// sigmoids and one coalesced 64B store.

#define HIDDEN 256
#define HALF   128
#define EPW    16    // edges per warp

__device__ __forceinline__ float sigmoidf(float v)
{
    return 1.0f / (1.0f + __expf(-v));
}

__global__ __launch_bounds__(256)
void edge_dot_sigmoid_kernel(const float* __restrict__ x,
                             const int* __restrict__ eidx,
                             float* __restrict__ out,
                             int n_edges)
{
    int warp = (blockIdx.x * blockDim.x + threadIdx.x) >> 5;
    int lane = threadIdx.x & 31;
    int base = warp * EPW;
    if (base >= n_edges) return;

    if (base + EPW <= n_edges) {
        // Warp-uniform vector index loads (16B requests).
        int s[EPW], d[EPW];
        #pragma unroll
        for (int g = 0; g < EPW / 4; g++) {
            int4 sv = __ldg(reinterpret_cast<const int4*>(eidx + base + 4 * g));
            int4 dv = __ldg(reinterpret_cast<const int4*>(eidx + n_edges + base + 4 * g));
            s[4*g+0] = sv.x; s[4*g+1] = sv.y; s[4*g+2] = sv.z; s[4*g+3] = sv.w;
            d[4*g+0] = dv.x; d[4*g+1] = dv.y; d[4*g+2] = dv.z; d[4*g+3] = dv.w;
        }

        // Issue all 32 gathers before any math.
        float4 a[EPW], b[EPW];
        #pragma unroll
        for (int k = 0; k < EPW; k++)
            a[k] = __ldg(reinterpret_cast<const float4*>(
                       x + (long long)s[k] * HIDDEN) + lane);
        #pragma unroll
        for (int k = 0; k < EPW; k++)
            b[k] = __ldg(reinterpret_cast<const float4*>(
                       x + (long long)d[k] * HIDDEN + HALF) + lane);

        float v[EPW];
        #pragma unroll
        for (int k = 0; k < EPW; k++)
            v[k] = a[k].x * b[k].x + a[k].y * b[k].y
                 + a[k].z * b[k].z + a[k].w * b[k].w;

        // Merging butterfly: 16 -> 8 -> 4 -> 2 -> 1 arrays, then final fold.
        float m0[8];
        #pragma unroll
        for (int k = 0; k < 8; k++) {
            float e0 = v[2*k]   + __shfl_xor_sync(0xffffffffu, v[2*k],   1);
            float e1 = v[2*k+1] + __shfl_xor_sync(0xffffffffu, v[2*k+1], 1);
            m0[k] = (lane & 1) ? e1 : e0;
        }
        float m1[4];
        #pragma unroll
        for (int k = 0; k < 4; k++) {
            float e0 = m0[2*k]   + __shfl_xor_sync(0xffffffffu, m0[2*k],   2);
            float e1 = m0[2*k+1] + __shfl_xor_sync(0xffffffffu, m0[2*k+1], 2);
            m1[k] = (lane & 2) ? e1 : e0;
        }
        float m2[2];
        #pragma unroll
        for (int k = 0; k < 2; k++) {
            float e0 = m1[2*k]   + __shfl_xor_sync(0xffffffffu, m1[2*k],   4);
            float e1 = m1[2*k+1] + __shfl_xor_sync(0xffffffffu, m1[2*k+1], 4);
            m2[k] = (lane & 4) ? e1 : e0;
        }
        float e0 = m2[0] + __shfl_xor_sync(0xffffffffu, m2[0], 8);
        float e1 = m2[1] + __shfl_xor_sync(0xffffffffu, m2[1], 8);
        float m3 = (lane & 8) ? e1 : e0;
        m3 += __shfl_xor_sync(0xffffffffu, m3, 16);
        // lane l now holds the full dot for edge (l & 15).

        if (lane < EPW)
            out[base + lane] = sigmoidf(m3);
    } else {
        // Tail: up to EPW-1 edges, scalar path.
        for (int e = base; e < n_edges; e++) {
            int s = __ldg(&eidx[e]);
            int d = __ldg(&eidx[n_edges + e]);
            float4 a = __ldg(reinterpret_cast<const float4*>(
                           x + (long long)s * HIDDEN) + lane);
            float4 b = __ldg(reinterpret_cast<const float4*>(
                           x + (long long)d * HIDDEN + HALF) + lane);
            float dot = a.x * b.x + a.y * b.y + a.z * b.z + a.w * b.w;
            #pragma unroll
            for (int off = 16; off > 0; off >>= 1)
                dot += __shfl_xor_sync(0xffffffffu, dot, off);
            if (lane == 0)
                out[e] = sigmoidf(dot);
        }
    }
}

extern "C" void kernel_launch(void* const* d_in, const int* in_sizes, int n_in,
                              void* d_out, int out_size)
{
    const float* x    = (const float*)d_in[0];
    const int*   eidx = (const int*)d_in[1];
    float*       out  = (float*)d_out;

    int n_edges = in_sizes[1] / 2;   // edge_label_index has 2*N_EDGES elements

    const int threads = 256;                       // 8 warps/block
    int warps_per_block = threads / 32;
    int edges_per_block = warps_per_block * EPW;
    int blocks = (n_edges + edges_per_block - 1) / edges_per_block;

    edge_dot_sigmoid_kernel<<<blocks, threads>>>(x, eidx, out, n_edges);
}